// round 1
// baseline (speedup 1.0000x reference)
#include <cuda_runtime.h>
#include <cstdint>

// ---------------------------------------------------------------------------
// DOMINANT: 4-layer GCN autoencoder.
//   deg[i] = indegree(i) + 1 (self loop);  dis = rsqrt(deg)
//   gcn(X,W,b): h = X@W;  out[d] += h[s]*dis[s]*dis[d] over edges
//               + h[i]*dis[i]^2 (self loop) + b
//   h1 = relu(gcn(x, W1,b1)); z = relu(gcn(h1, W2,b2));
//   xh = relu(gcn(z, W3,b3)); x_hat = gcn(xh, W4,b4)
//   output = concat(x_hat [N,128], z [N,64])
// ---------------------------------------------------------------------------

#define MAXN 50000
#define MAXE 640000

__device__ float g_h[(size_t)MAXN * 128];   // post-GEMM features (max D=128)
__device__ float g_buf[(size_t)MAXN * 64];  // layer outputs h1 / xh
__device__ float g_dis[MAXN];               // deg, then rsqrt(deg)
__device__ int   g_src[MAXE];
__device__ int   g_dst[MAXE];
__device__ float g_norm[MAXE];
__device__ int   g_flag;                    // 1 => edge_index stored as int32

// --- dtype detection: int64 data has all values < 50000; int32 data read as
// int64 pairs lo + (hi<<32) and hi is ~uniform in [0,50000) -> huge values.
__global__ void detect_kernel(const long long* __restrict__ p, int cnt) {
    __shared__ int bad;
    if (threadIdx.x == 0) bad = 0;
    __syncthreads();
    int lb = 0;
    for (int i = threadIdx.x; i < cnt; i += blockDim.x) {
        long long v = p[i];
        if (v < 0 || v > 0x7fffffffLL) lb = 1;
    }
    if (lb) atomicOr(&bad, 1);
    __syncthreads();
    if (threadIdx.x == 0) g_flag = bad;
}

__global__ void deg_init_kernel(int n) {
    int i = blockIdx.x * blockDim.x + threadIdx.x;
    if (i < n) g_dis[i] = 1.0f;   // self loop contributes 1 to degree
}

__global__ void decode_edges_kernel(const void* __restrict__ ei, int E) {
    int e = blockIdx.x * blockDim.x + threadIdx.x;
    if (e >= E) return;
    int s, d;
    if (g_flag) {
        const int* p = (const int*)ei;
        s = p[e];
        d = p[E + e];
    } else {
        const long long* p = (const long long*)ei;
        s = (int)p[e];
        d = (int)p[(size_t)E + e];
    }
    g_src[e] = s;
    g_dst[e] = d;
    atomicAdd(&g_dis[d], 1.0f);
}

__global__ void dis_kernel(int n) {
    int i = blockIdx.x * blockDim.x + threadIdx.x;
    if (i < n) g_dis[i] = rsqrtf(g_dis[i]);
}

__global__ void norm_kernel(int E) {
    int e = blockIdx.x * blockDim.x + threadIdx.x;
    if (e >= E) return;
    g_norm[e] = g_dis[g_src[e]] * g_dis[g_dst[e]];
}

// --- register-tiled fp32 GEMM: Y[n,DOUT] = (relu?)X[n,K] @ W[K,DOUT]
// 256 threads; thread tile R rows x 4 cols.
template <int K, int DOUT, int R, bool RELU_IN>
__global__ __launch_bounds__(256) void gemm_kernel(
    const float* __restrict__ X, const float* __restrict__ W,
    float* __restrict__ Y, int n)
{
    constexpr int CG = DOUT / 4;       // column groups (float4)
    constexpr int RG = 256 / CG;       // row groups
    constexpr int ROWS = RG * R;       // rows per block
    __shared__ float Ws[K * DOUT];
    __shared__ float Xs[ROWS * K];

    const int t = threadIdx.x;
    const int row0 = blockIdx.x * ROWS;

    for (int i = t; i < K * DOUT / 4; i += 256)
        ((float4*)Ws)[i] = ((const float4*)W)[i];

    for (int i = t; i < ROWS * K / 4; i += 256) {
        int pos = i * 4;
        int r = pos / K;
        int k = pos % K;
        int gr = row0 + r;
        float4 v = make_float4(0.f, 0.f, 0.f, 0.f);
        if (gr < n) v = *(const float4*)&X[(size_t)gr * K + k];
        if (RELU_IN) {
            v.x = fmaxf(v.x, 0.f); v.y = fmaxf(v.y, 0.f);
            v.z = fmaxf(v.z, 0.f); v.w = fmaxf(v.w, 0.f);
        }
        *(float4*)&Xs[r * K + k] = v;
    }
    __syncthreads();

    const int cg = t % CG;
    const int rg = t / CG;

    float acc[R][4];
#pragma unroll
    for (int r = 0; r < R; r++)
#pragma unroll
        for (int c = 0; c < 4; c++) acc[r][c] = 0.f;

#pragma unroll 4
    for (int k = 0; k < K; k++) {
        float4 w = *(const float4*)&Ws[k * DOUT + cg * 4];
#pragma unroll
        for (int r = 0; r < R; r++) {
            float xv = Xs[(rg * R + r) * K + k];
            acc[r][0] += xv * w.x;
            acc[r][1] += xv * w.y;
            acc[r][2] += xv * w.z;
            acc[r][3] += xv * w.w;
        }
    }

#pragma unroll
    for (int r = 0; r < R; r++) {
        int gr = row0 + rg * R + r;
        if (gr < n)
            *(float4*)&Y[(size_t)gr * DOUT + cg * 4] =
                make_float4(acc[r][0], acc[r][1], acc[r][2], acc[r][3]);
    }
}

// --- aggregation init: out = h*dis^2 (self loop) + b
template <int D>
__global__ void agg_init_kernel(const float* __restrict__ H,
                                const float* __restrict__ b,
                                float* __restrict__ out, int n)
{
    int idx = blockIdx.x * blockDim.x + threadIdx.x;  // float4 index
    int total = n * (D / 4);
    if (idx >= total) return;
    int node = idx / (D / 4);
    int c4 = idx % (D / 4);
    float s = g_dis[node];
    s = s * s;
    float4 h = ((const float4*)H)[idx];
    float4 bb = *(const float4*)&b[c4 * 4];
    float4 o;
    o.x = h.x * s + bb.x;
    o.y = h.y * s + bb.y;
    o.z = h.z * s + bb.z;
    o.w = h.w * s + bb.w;
    ((float4*)out)[idx] = o;
}

// --- edge scatter: out[dst] += h[src]*norm, D/4 threads per edge
template <int D>
__global__ void agg_edges_kernel(const float* __restrict__ H,
                                 float* __restrict__ out, int E)
{
    constexpr int TPE = D / 4;
    long long tid = (long long)blockIdx.x * blockDim.x + threadIdx.x;
    int e = (int)(tid / TPE);
    int c = (int)(tid % TPE);
    if (e >= E) return;
    int s = g_src[e];
    int d = g_dst[e];
    float nm = g_norm[e];
    float4 h = *(const float4*)&H[(size_t)s * D + c * 4];
    float* o = &out[(size_t)d * D + c * 4];
    atomicAdd(o + 0, h.x * nm);
    atomicAdd(o + 1, h.y * nm);
    atomicAdd(o + 2, h.z * nm);
    atomicAdd(o + 3, h.w * nm);
}

__global__ void relu_kernel(float* __restrict__ p, int n4) {
    int i = blockIdx.x * blockDim.x + threadIdx.x;
    if (i >= n4) return;
    float4 v = ((float4*)p)[i];
    v.x = fmaxf(v.x, 0.f); v.y = fmaxf(v.y, 0.f);
    v.z = fmaxf(v.z, 0.f); v.w = fmaxf(v.w, 0.f);
    ((float4*)p)[i] = v;
}

static inline int ceil_div(long long a, int b) { return (int)((a + b - 1) / b); }

extern "C" void kernel_launch(void* const* d_in, const int* in_sizes, int n_in,
                              void* d_out, int out_size)
{
    const float* x  = (const float*)d_in[0];
    const void*  ei = d_in[1];
    const float* W1 = (const float*)d_in[2];
    const float* b1 = (const float*)d_in[3];
    const float* W2 = (const float*)d_in[4];
    const float* b2 = (const float*)d_in[5];
    const float* W3 = (const float*)d_in[6];
    const float* b3 = (const float*)d_in[7];
    const float* W4 = (const float*)d_in[8];
    const float* b4 = (const float*)d_in[9];

    const int N = in_sizes[0] / 128;
    const int E = in_sizes[1] / 2;

    float* out  = (float*)d_out;
    float* xhat = out;                       // [N,128]
    float* z    = out + (size_t)N * 128;     // [N,64]

    float* hbuf;  cudaGetSymbolAddress((void**)&hbuf, g_h);
    float* abuf;  cudaGetSymbolAddress((void**)&abuf, g_buf);

    // --- graph prep ---
    detect_kernel<<<1, 256>>>((const long long*)ei, 4096);
    deg_init_kernel<<<ceil_div(N, 256), 256>>>(N);
    decode_edges_kernel<<<ceil_div(E, 256), 256>>>(ei, E);
    dis_kernel<<<ceil_div(N, 256), 256>>>(N);
    norm_kernel<<<ceil_div(E, 256), 256>>>(E);

    // --- layer 1: x[128] -> h1[64] (relu fused into layer-2 gemm load) ---
    gemm_kernel<128, 64, 2, false><<<ceil_div(N, 32), 256>>>(x, W1, hbuf, N);
    agg_init_kernel<64><<<ceil_div((long long)N * 16, 256), 256>>>(hbuf, b1, abuf, N);
    agg_edges_kernel<64><<<ceil_div((long long)E * 16, 256), 256>>>(hbuf, abuf, E);

    // --- layer 2: h1[64] -> z[64] (relu materialized: z is an output) ---
    gemm_kernel<64, 64, 4, true><<<ceil_div(N, 64), 256>>>(abuf, W2, hbuf, N);
    agg_init_kernel<64><<<ceil_div((long long)N * 16, 256), 256>>>(hbuf, b2, z, N);
    agg_edges_kernel<64><<<ceil_div((long long)E * 16, 256), 256>>>(hbuf, z, E);
    relu_kernel<<<ceil_div((long long)N * 16, 256), 256>>>(z, N * 16);

    // --- layer 3: z[64] -> xh[64] (relu fused into layer-4 gemm load) ---
    gemm_kernel<64, 64, 4, false><<<ceil_div(N, 64), 256>>>(z, W3, hbuf, N);
    agg_init_kernel<64><<<ceil_div((long long)N * 16, 256), 256>>>(hbuf, b3, abuf, N);
    agg_edges_kernel<64><<<ceil_div((long long)E * 16, 256), 256>>>(hbuf, abuf, E);

    // --- layer 4: xh[64] -> x_hat[128] (no relu) ---
    gemm_kernel<64, 128, 4, true><<<ceil_div(N, 32), 256>>>(abuf, W4, hbuf, N);
    agg_init_kernel<128><<<ceil_div((long long)N * 32, 256), 256>>>(hbuf, b4, xhat, N);
    agg_edges_kernel<128><<<ceil_div((long long)E * 32, 256), 256>>>(hbuf, xhat, E);
}

// round 2
// speedup vs baseline: 2.4969x; 2.4969x over previous
#include <cuda_runtime.h>
#include <cstdint>

// ---------------------------------------------------------------------------
// DOMINANT 4-layer GCN autoencoder, CSR gather-based aggregation (no atomics
// in the hot path).
//   L1: h=x@W1;            abuf = relu(A_hat h + b1)
//   L2: h=abuf@W2;         z    = relu(A_hat h + b2)
//   L3: h=z@W3;            abuf = relu(A_hat h + b3)
//   L4: hbuf=A_hat abuf;   x_hat = hbuf@W4 + b4        (A(XW) == (AX)W)
//   out = concat(x_hat[N,128], z[N,64])
// ---------------------------------------------------------------------------

#define MAXN 50048
#define MAXE 640000

__device__ float g_h[(size_t)MAXN * 64];    // post-GEMM features (D=64)
__device__ float g_buf[(size_t)MAXN * 64];  // layer outputs h1 / xh / agg4
__device__ float g_dis[MAXN];               // rsqrt(deg+1)
__device__ int   g_deg[MAXN];               // in-degree (edges only)
__device__ int   g_off[MAXN];               // CSR exclusive offsets
__device__ int   g_cur[MAXN];               // scatter cursors
__device__ int   g_part[1024];              // scan partials
__device__ int   g_src[MAXE];
__device__ int   g_dst[MAXE];
__device__ int   g_csrc[MAXE];              // CSR src per slot
__device__ float g_cnorm[MAXE];             // CSR norm per slot
__device__ int   g_flag;                    // 1 => edge_index is int32

// --- dtype detection: true int64 indices are all < 50000; int32 data
// reinterpreted as int64 yields values >= 2^32 w.h.p. over 4096 samples.
__global__ void detect_kernel(const long long* __restrict__ p, int cnt) {
    __shared__ int bad;
    if (threadIdx.x == 0) bad = 0;
    __syncthreads();
    int lb = 0;
    for (int i = threadIdx.x; i < cnt; i += blockDim.x) {
        long long v = p[i];
        if (v < 0 || v > 0x7fffffffLL) lb = 1;
    }
    if (lb) atomicOr(&bad, 1);
    __syncthreads();
    if (threadIdx.x == 0) g_flag = bad;
}

__global__ void zero_deg_kernel(int n) {
    int i = blockIdx.x * blockDim.x + threadIdx.x;
    if (i < n) g_deg[i] = 0;
}

__global__ void decode_count_kernel(const void* __restrict__ ei, int E) {
    int e = blockIdx.x * blockDim.x + threadIdx.x;
    if (e >= E) return;
    int s, d;
    if (g_flag) {
        const int* p = (const int*)ei;
        s = p[e]; d = p[E + e];
    } else {
        const long long* p = (const long long*)ei;
        s = (int)p[e]; d = (int)p[(size_t)E + e];
    }
    g_src[e] = s;
    g_dst[e] = d;
    atomicAdd(&g_deg[d], 1);
}

__global__ void dis_kernel(int n) {
    int i = blockIdx.x * blockDim.x + threadIdx.x;
    if (i < n) g_dis[i] = rsqrtf((float)(g_deg[i] + 1));
}

// --- 3-phase exclusive scan of g_deg into g_off (N <= 256*1024) ---
__global__ void scan_block_kernel(int n) {
    __shared__ int sh[256];
    int i = blockIdx.x * 256 + threadIdx.x;
    int v = (i < n) ? g_deg[i] : 0;
    sh[threadIdx.x] = v;
    __syncthreads();
#pragma unroll
    for (int ofs = 1; ofs < 256; ofs <<= 1) {
        int t = (threadIdx.x >= ofs) ? sh[threadIdx.x - ofs] : 0;
        __syncthreads();
        sh[threadIdx.x] += t;
        __syncthreads();
    }
    if (i < n) g_off[i] = sh[threadIdx.x] - v;   // exclusive
    if (threadIdx.x == 255) g_part[blockIdx.x] = sh[255];
}

__global__ void scan_part_kernel(int nb) {
    __shared__ int sh[1024];
    int v = (threadIdx.x < nb) ? g_part[threadIdx.x] : 0;
    sh[threadIdx.x] = v;
    __syncthreads();
#pragma unroll
    for (int ofs = 1; ofs < 1024; ofs <<= 1) {
        int t = (threadIdx.x >= ofs) ? sh[threadIdx.x - ofs] : 0;
        __syncthreads();
        sh[threadIdx.x] += t;
        __syncthreads();
    }
    if (threadIdx.x < nb) g_part[threadIdx.x] = sh[threadIdx.x] - v;  // exclusive
}

__global__ void scan_add_kernel(int n) {
    int i = blockIdx.x * blockDim.x + threadIdx.x;
    if (i < n) {
        g_off[i] += g_part[i >> 8];
        g_cur[i] = 0;
    }
}

__global__ void csr_scatter_kernel(int E) {
    int e = blockIdx.x * blockDim.x + threadIdx.x;
    if (e >= E) return;
    int s = g_src[e];
    int d = g_dst[e];
    int pos = g_off[d] + atomicAdd(&g_cur[d], 1);
    g_csrc[pos] = s;
    g_cnorm[pos] = g_dis[s] * g_dis[d];
}

// --- register-tiled fp32 GEMM: Y[n,DOUT] = X[n,K] @ W[K,DOUT] (+b)
template <int K, int DOUT, int R, bool BIAS>
__global__ __launch_bounds__(256) void gemm_kernel(
    const float* __restrict__ X, const float* __restrict__ W,
    const float* __restrict__ b, float* __restrict__ Y, int n)
{
    constexpr int CG = DOUT / 4;
    constexpr int RG = 256 / CG;
    constexpr int ROWS = RG * R;
    __shared__ float Ws[K * DOUT];
    __shared__ float Xs[ROWS * K];

    const int t = threadIdx.x;
    const int row0 = blockIdx.x * ROWS;

    for (int i = t; i < K * DOUT / 4; i += 256)
        ((float4*)Ws)[i] = ((const float4*)W)[i];

    for (int i = t; i < ROWS * K / 4; i += 256) {
        int pos = i * 4;
        int r = pos / K;
        int k = pos % K;
        int gr = row0 + r;
        float4 v = make_float4(0.f, 0.f, 0.f, 0.f);
        if (gr < n) v = *(const float4*)&X[(size_t)gr * K + k];
        *(float4*)&Xs[r * K + k] = v;
    }
    __syncthreads();

    const int cg = t % CG;
    const int rg = t / CG;

    float acc[R][4];
#pragma unroll
    for (int r = 0; r < R; r++)
#pragma unroll
        for (int c = 0; c < 4; c++) acc[r][c] = 0.f;

#pragma unroll 4
    for (int k = 0; k < K; k++) {
        float4 w = *(const float4*)&Ws[k * DOUT + cg * 4];
#pragma unroll
        for (int r = 0; r < R; r++) {
            float xv = Xs[(rg * R + r) * K + k];
            acc[r][0] += xv * w.x;
            acc[r][1] += xv * w.y;
            acc[r][2] += xv * w.z;
            acc[r][3] += xv * w.w;
        }
    }

    float4 bb = make_float4(0.f, 0.f, 0.f, 0.f);
    if (BIAS) bb = *(const float4*)&b[cg * 4];

#pragma unroll
    for (int r = 0; r < R; r++) {
        int gr = row0 + rg * R + r;
        if (gr < n)
            *(float4*)&Y[(size_t)gr * DOUT + cg * 4] =
                make_float4(acc[r][0] + bb.x, acc[r][1] + bb.y,
                            acc[r][2] + bb.z, acc[r][3] + bb.w);
    }
}

// --- gather aggregation over CSR: out[i] = (relu)(sum_{e in in(i)} h[src_e]*norm_e
//                                          + h[i]*dis_i^2 (+ b))
// D=64 fixed: 16 threads per node, one float4 column each.
template <bool BIAS, bool RELU>
__global__ __launch_bounds__(256) void agg_gather_kernel(
    const float* __restrict__ H, const float* __restrict__ b,
    float* __restrict__ out, int n)
{
    int node = blockIdx.x * 16 + (threadIdx.x >> 4);
    int c = threadIdx.x & 15;
    if (node >= n) return;

    const float4* H4 = (const float4*)H;
    float dis = g_dis[node];
    float s2 = dis * dis;

    float4 hv = H4[(size_t)node * 16 + c];
    float4 acc;
    acc.x = hv.x * s2; acc.y = hv.y * s2;
    acc.z = hv.z * s2; acc.w = hv.w * s2;
    if (BIAS) {
        float4 bb = *(const float4*)&b[c * 4];
        acc.x += bb.x; acc.y += bb.y; acc.z += bb.z; acc.w += bb.w;
    }

    int beg = g_off[node];
    int end = beg + g_deg[node];
    int e = beg;
    // 2-deep software pipeline for MLP
    for (; e + 1 < end; e += 2) {
        int s0 = g_csrc[e];     float n0 = g_cnorm[e];
        int s1 = g_csrc[e + 1]; float n1 = g_cnorm[e + 1];
        float4 h0 = H4[(size_t)s0 * 16 + c];
        float4 h1 = H4[(size_t)s1 * 16 + c];
        acc.x += h0.x * n0; acc.y += h0.y * n0;
        acc.z += h0.z * n0; acc.w += h0.w * n0;
        acc.x += h1.x * n1; acc.y += h1.y * n1;
        acc.z += h1.z * n1; acc.w += h1.w * n1;
    }
    if (e < end) {
        int s0 = g_csrc[e]; float n0 = g_cnorm[e];
        float4 h0 = H4[(size_t)s0 * 16 + c];
        acc.x += h0.x * n0; acc.y += h0.y * n0;
        acc.z += h0.z * n0; acc.w += h0.w * n0;
    }

    if (RELU) {
        acc.x = fmaxf(acc.x, 0.f); acc.y = fmaxf(acc.y, 0.f);
        acc.z = fmaxf(acc.z, 0.f); acc.w = fmaxf(acc.w, 0.f);
    }
    ((float4*)out)[(size_t)node * 16 + c] = acc;
}

static inline int ceil_div(long long a, int bsz) { return (int)((a + bsz - 1) / bsz); }

extern "C" void kernel_launch(void* const* d_in, const int* in_sizes, int n_in,
                              void* d_out, int out_size)
{
    const float* x  = (const float*)d_in[0];
    const void*  ei = d_in[1];
    const float* W1 = (const float*)d_in[2];
    const float* b1 = (const float*)d_in[3];
    const float* W2 = (const float*)d_in[4];
    const float* b2 = (const float*)d_in[5];
    const float* W3 = (const float*)d_in[6];
    const float* b3 = (const float*)d_in[7];
    const float* W4 = (const float*)d_in[8];
    const float* b4 = (const float*)d_in[9];

    const int N = in_sizes[0] / 128;
    const int E = in_sizes[1] / 2;

    float* out  = (float*)d_out;
    float* xhat = out;                       // [N,128]
    float* z    = out + (size_t)N * 128;     // [N,64]

    float* hbuf;  cudaGetSymbolAddress((void**)&hbuf, g_h);
    float* abuf;  cudaGetSymbolAddress((void**)&abuf, g_buf);

    const int nb = ceil_div(N, 256);

    // --- graph prep: decode edges, degrees, CSR build ---
    detect_kernel<<<1, 256>>>((const long long*)ei, 4096);
    zero_deg_kernel<<<nb, 256>>>(N);
    decode_count_kernel<<<ceil_div(E, 256), 256>>>(ei, E);
    dis_kernel<<<nb, 256>>>(N);
    scan_block_kernel<<<nb, 256>>>(N);
    scan_part_kernel<<<1, 1024>>>(nb);
    scan_add_kernel<<<nb, 256>>>(N);
    csr_scatter_kernel<<<ceil_div(E, 256), 256>>>(E);

    // --- layer 1: x[128]@W1 -> h[64]; abuf = relu(A_hat h + b1) ---
    gemm_kernel<128, 64, 2, false><<<ceil_div(N, 32), 256>>>(x, W1, nullptr, hbuf, N);
    agg_gather_kernel<true, true><<<ceil_div(N, 16), 256>>>(hbuf, b1, abuf, N);

    // --- layer 2: abuf@W2 -> h; z = relu(A_hat h + b2) ---
    gemm_kernel<64, 64, 4, false><<<ceil_div(N, 64), 256>>>(abuf, W2, nullptr, hbuf, N);
    agg_gather_kernel<true, true><<<ceil_div(N, 16), 256>>>(hbuf, b2, z, N);

    // --- layer 3: z@W3 -> h; abuf = relu(A_hat h + b3) ---
    gemm_kernel<64, 64, 4, false><<<ceil_div(N, 64), 256>>>(z, W3, nullptr, hbuf, N);
    agg_gather_kernel<true, true><<<ceil_div(N, 16), 256>>>(hbuf, b3, abuf, N);

    // --- layer 4: hbuf = A_hat abuf (no bias/relu); x_hat = hbuf@W4 + b4 ---
    agg_gather_kernel<false, false><<<ceil_div(N, 16), 256>>>(abuf, nullptr, hbuf, N);
    gemm_kernel<64, 128, 4, true><<<ceil_div(N, 32), 256>>>(hbuf, W4, b4, xhat, N);
}

// round 4
// speedup vs baseline: 2.7613x; 1.1059x over previous
#include <cuda_runtime.h>
#include <cstdint>

// ---------------------------------------------------------------------------
// DOMINANT 4-layer GCN autoencoder.
// CSR gather-based aggregation (no atomics in hot path) + packed-f32x2 GEMMs.
//   L1: h=x@W1;            abuf = relu(A_hat h + b1)
//   L2: h=abuf@W2;         z    = relu(A_hat h + b2)
//   L3: h=z@W3;            abuf = relu(A_hat h + b3)
//   L4: hbuf=A_hat abuf;   x_hat = hbuf@W4 + b4        (A(XW) == (AX)W)
//   out = concat(x_hat[N,128], z[N,64])
// GEMM inner loop uses PTX fma.rn.f32x2 (Blackwell FFMA2): 2 fp32 MACs per
// fma-pipe issue slot. X tile stored as duplicated 64-bit pairs in smem so
// the broadcast needs no extra MOV.
// ---------------------------------------------------------------------------

#define MAXN 50048
#define MAXE 640000

__device__ float g_h[(size_t)MAXN * 64];    // post-GEMM features (D=64)
__device__ float g_buf[(size_t)MAXN * 64];  // layer outputs h1 / xh / agg4
__device__ float g_dis[MAXN];               // rsqrt(deg+1)
__device__ int   g_deg[MAXN];               // in-degree (edges only)
__device__ int   g_off[MAXN];               // CSR exclusive offsets
__device__ int   g_cur[MAXN];               // scatter cursors
__device__ int   g_part[1024];              // scan partials
__device__ int   g_src[MAXE];
__device__ int   g_dst[MAXE];
__device__ int   g_csrc[MAXE];              // CSR src per slot
__device__ float g_cnorm[MAXE];             // CSR norm per slot
__device__ int   g_flag;                    // 1 => edge_index is int32

// ========================= graph prep kernels ==============================
// zero g_deg; block 0 also detects edge dtype (int64 values all < 50000;
// int32 data reinterpreted as int64 yields values >= 2^32 w.h.p.)
__global__ void detect_zero_kernel(const long long* __restrict__ p, int cnt, int n) {
    int i = blockIdx.x * blockDim.x + threadIdx.x;
    if (i < n) g_deg[i] = 0;
    if (blockIdx.x == 0) {
        __shared__ int bad;
        if (threadIdx.x == 0) bad = 0;
        __syncthreads();
        int lb = 0;
        for (int j = threadIdx.x; j < cnt; j += blockDim.x) {
            long long v = p[j];
            if (v < 0 || v > 0x7fffffffLL) lb = 1;
        }
        if (lb) atomicOr(&bad, 1);
        __syncthreads();
        if (threadIdx.x == 0) g_flag = bad;
    }
}

__global__ void decode_count_kernel(const void* __restrict__ ei, int E) {
    int e = blockIdx.x * blockDim.x + threadIdx.x;
    if (e >= E) return;
    int s, d;
    if (g_flag) {
        const int* p = (const int*)ei;
        s = p[e]; d = p[E + e];
    } else {
        const long long* p = (const long long*)ei;
        s = (int)p[e]; d = (int)p[(size_t)E + e];
    }
    g_src[e] = s;
    g_dst[e] = d;
    atomicAdd(&g_deg[d], 1);
}

// fused: g_dis = rsqrt(deg+1)  +  per-block exclusive scan of g_deg
__global__ void dis_scan_kernel(int n) {
    __shared__ int sh[256];
    int i = blockIdx.x * 256 + threadIdx.x;
    int v = 0;
    if (i < n) {
        v = g_deg[i];
        g_dis[i] = rsqrtf((float)(v + 1));
    }
    sh[threadIdx.x] = v;
    __syncthreads();
#pragma unroll
    for (int ofs = 1; ofs < 256; ofs <<= 1) {
        int t = (threadIdx.x >= ofs) ? sh[threadIdx.x - ofs] : 0;
        __syncthreads();
        sh[threadIdx.x] += t;
        __syncthreads();
    }
    if (i < n) g_off[i] = sh[threadIdx.x] - v;
    if (threadIdx.x == 255) g_part[blockIdx.x] = sh[255];
}

__global__ void scan_part_kernel(int nb) {
    __shared__ int sh[1024];
    int v = (threadIdx.x < nb) ? g_part[threadIdx.x] : 0;
    sh[threadIdx.x] = v;
    __syncthreads();
#pragma unroll
    for (int ofs = 1; ofs < 1024; ofs <<= 1) {
        int t = (threadIdx.x >= ofs) ? sh[threadIdx.x - ofs] : 0;
        __syncthreads();
        sh[threadIdx.x] += t;
        __syncthreads();
    }
    if (threadIdx.x < nb) g_part[threadIdx.x] = sh[threadIdx.x] - v;
}

__global__ void scan_add_kernel(int n) {
    int i = blockIdx.x * blockDim.x + threadIdx.x;
    if (i < n) {
        g_off[i] += g_part[i >> 8];
        g_cur[i] = 0;
    }
}

__global__ void csr_scatter_kernel(int E) {
    int e = blockIdx.x * blockDim.x + threadIdx.x;
    if (e >= E) return;
    int s = g_src[e];
    int d = g_dst[e];
    int pos = g_off[d] + atomicAdd(&g_cur[d], 1);
    g_csrc[pos] = s;
    g_cnorm[pos] = g_dis[s] * g_dis[d];
}

// ===================== packed-f32x2 GEMM ===================================
// Y[n,DOUT] = X[n,K] @ W[K,DOUT] (+b). 256 threads; thread tile R rows x 4
// cols held as 2 packed f32x2 accumulators per row.
// Dynamic smem: Ws[K*DOUT] floats, then Xs2[ROWS*K] u64 (x duplicated lo==hi).
template <int K, int DOUT, int R, bool BIAS>
__global__ __launch_bounds__(256) void gemm_kernel(
    const float* __restrict__ X, const float* __restrict__ W,
    const float* __restrict__ b, float* __restrict__ Y, int n)
{
    constexpr int CG = DOUT / 4;
    constexpr int RG = 256 / CG;
    constexpr int ROWS = RG * R;

    extern __shared__ char dyn[];
    float* Ws = (float*)dyn;                                  // K*DOUT floats
    unsigned long long* Xs2 = (unsigned long long*)(dyn + (size_t)K * DOUT * 4);

    const int t = threadIdx.x;
    const int row0 = blockIdx.x * ROWS;

    for (int i = t; i < K * DOUT / 4; i += 256)
        ((float4*)Ws)[i] = ((const float4*)W)[i];

    for (int i = t; i < ROWS * K / 4; i += 256) {
        int pos = i * 4;
        int r = pos / K;
        int k = pos % K;
        int gr = row0 + r;
        float4 v = make_float4(0.f, 0.f, 0.f, 0.f);
        if (gr < n) v = *(const float4*)&X[(size_t)gr * K + k];
        unsigned long long d0, d1, d2, d3;
        asm("mov.b64 %0, {%1, %1};" : "=l"(d0) : "f"(v.x));
        asm("mov.b64 %0, {%1, %1};" : "=l"(d1) : "f"(v.y));
        asm("mov.b64 %0, {%1, %1};" : "=l"(d2) : "f"(v.z));
        asm("mov.b64 %0, {%1, %1};" : "=l"(d3) : "f"(v.w));
        unsigned long long* p = &Xs2[r * K + k];
        p[0] = d0; p[1] = d1; p[2] = d2; p[3] = d3;
    }
    __syncthreads();

    const int cg = t % CG;
    const int rg = t / CG;

    unsigned long long acc[R][2];   // each holds two packed fp32 (init +0,+0)
#pragma unroll
    for (int r = 0; r < R; r++) { acc[r][0] = 0ull; acc[r][1] = 0ull; }

#pragma unroll 4
    for (int k = 0; k < K; k++) {
        ulonglong2 w = *(const ulonglong2*)&Ws[k * DOUT + cg * 4];
#pragma unroll
        for (int r = 0; r < R; r++) {
            unsigned long long x2 = Xs2[(rg * R + r) * K + k];
            asm("fma.rn.f32x2 %0, %1, %2, %0;" : "+l"(acc[r][0]) : "l"(x2), "l"(w.x));
            asm("fma.rn.f32x2 %0, %1, %2, %0;" : "+l"(acc[r][1]) : "l"(x2), "l"(w.y));
        }
    }

    float4 bb = make_float4(0.f, 0.f, 0.f, 0.f);
    if (BIAS) bb = *(const float4*)&b[cg * 4];

#pragma unroll
    for (int r = 0; r < R; r++) {
        int gr = row0 + rg * R + r;
        if (gr < n) {
            float o0, o1, o2, o3;
            asm("mov.b64 {%0, %1}, %2;" : "=f"(o0), "=f"(o1) : "l"(acc[r][0]));
            asm("mov.b64 {%0, %1}, %2;" : "=f"(o2), "=f"(o3) : "l"(acc[r][1]));
            *(float4*)&Y[(size_t)gr * DOUT + cg * 4] =
                make_float4(o0 + bb.x, o1 + bb.y, o2 + bb.z, o3 + bb.w);
        }
    }
}

// ===================== CSR gather aggregation ==============================
// out[i] = (relu)(sum_{e in in(i)} h[src_e]*norm_e + h[i]*dis_i^2 (+ b))
// D=64: 16 threads per node, one float4 column each.
template <bool BIAS, bool RELU>
__global__ __launch_bounds__(256) void agg_gather_kernel(
    const float* __restrict__ H, const float* __restrict__ b,
    float* __restrict__ out, int n)
{
    int node = blockIdx.x * 16 + (threadIdx.x >> 4);
    int c = threadIdx.x & 15;
    if (node >= n) return;

    const float4* H4 = (const float4*)H;
    float dis = g_dis[node];
    float s2 = dis * dis;

    float4 hv = H4[(size_t)node * 16 + c];
    float4 acc;
    acc.x = hv.x * s2; acc.y = hv.y * s2;
    acc.z = hv.z * s2; acc.w = hv.w * s2;
    if (BIAS) {
        float4 bb = *(const float4*)&b[c * 4];
        acc.x += bb.x; acc.y += bb.y; acc.z += bb.z; acc.w += bb.w;
    }

    int beg = g_off[node];
    int end = beg + g_deg[node];
    int e = beg;
    for (; e + 1 < end; e += 2) {
        int s0 = g_csrc[e];     float n0 = g_cnorm[e];
        int s1 = g_csrc[e + 1]; float n1 = g_cnorm[e + 1];
        float4 h0 = H4[(size_t)s0 * 16 + c];
        float4 h1 = H4[(size_t)s1 * 16 + c];
        acc.x += h0.x * n0; acc.y += h0.y * n0;
        acc.z += h0.z * n0; acc.w += h0.w * n0;
        acc.x += h1.x * n1; acc.y += h1.y * n1;
        acc.z += h1.z * n1; acc.w += h1.w * n1;
    }
    if (e < end) {
        int s0 = g_csrc[e]; float n0 = g_cnorm[e];
        float4 h0 = H4[(size_t)s0 * 16 + c];
        acc.x += h0.x * n0; acc.y += h0.y * n0;
        acc.z += h0.z * n0; acc.w += h0.w * n0;
    }

    if (RELU) {
        acc.x = fmaxf(acc.x, 0.f); acc.y = fmaxf(acc.y, 0.f);
        acc.z = fmaxf(acc.z, 0.f); acc.w = fmaxf(acc.w, 0.f);
    }
    ((float4*)out)[(size_t)node * 16 + c] = acc;
}

static inline int ceil_div(long long a, int bsz) { return (int)((a + bsz - 1) / bsz); }

extern "C" void kernel_launch(void* const* d_in, const int* in_sizes, int n_in,
                              void* d_out, int out_size)
{
    const float* x  = (const float*)d_in[0];
    const void*  ei = d_in[1];
    const float* W1 = (const float*)d_in[2];
    const float* b1 = (const float*)d_in[3];
    const float* W2 = (const float*)d_in[4];
    const float* b2 = (const float*)d_in[5];
    const float* W3 = (const float*)d_in[6];
    const float* b3 = (const float*)d_in[7];
    const float* W4 = (const float*)d_in[8];
    const float* b4 = (const float*)d_in[9];

    const int N = in_sizes[0] / 128;
    const int E = in_sizes[1] / 2;

    float* out  = (float*)d_out;
    float* xhat = out;                       // [N,128]
    float* z    = out + (size_t)N * 128;     // [N,64]

    float* hbuf;  cudaGetSymbolAddress((void**)&hbuf, g_h);
    float* abuf;  cudaGetSymbolAddress((void**)&abuf, g_buf);

    // dynamic smem sizes: Ws (K*DOUT*4) + Xs2 (ROWS*K*8)
    const int SM_L1 = 128 * 64 * 4 + 64 * 128 * 8;   // R=4, ROWS=64: 32K+64K=96K
    const int SM_L2 = 64 * 64 * 4 + 64 * 64 * 8;     // R=4, ROWS=64: 16K+32K=48K
    const int SM_L4 = 64 * 128 * 4 + 32 * 64 * 8;    // R=4, ROWS=32: 32K+16K=48K
    static bool attr_done = false;
    if (!attr_done) {
        cudaFuncSetAttribute(gemm_kernel<128, 64, 4, false>,
                             cudaFuncAttributeMaxDynamicSharedMemorySize, SM_L1);
        cudaFuncSetAttribute(gemm_kernel<64, 64, 4, false>,
                             cudaFuncAttributeMaxDynamicSharedMemorySize, SM_L2);
        cudaFuncSetAttribute(gemm_kernel<64, 128, 4, true>,
                             cudaFuncAttributeMaxDynamicSharedMemorySize, SM_L4);
        attr_done = true;
    }

    const int nb = ceil_div(N, 256);

    // --- graph prep: 6 launches ---
    detect_zero_kernel<<<nb, 256>>>((const long long*)ei, 4096, N);
    decode_count_kernel<<<ceil_div(E, 256), 256>>>(ei, E);
    dis_scan_kernel<<<nb, 256>>>(N);
    scan_part_kernel<<<1, 1024>>>(nb);
    scan_add_kernel<<<nb, 256>>>(N);
    csr_scatter_kernel<<<ceil_div(E, 256), 256>>>(E);

    // --- layer 1: x[128]@W1 -> h[64]; abuf = relu(A_hat h + b1) ---
    gemm_kernel<128, 64, 4, false><<<ceil_div(N, 64), 256, SM_L1>>>(x, W1, nullptr, hbuf, N);
    agg_gather_kernel<true, true><<<ceil_div(N, 16), 256>>>(hbuf, b1, abuf, N);

    // --- layer 2: abuf@W2 -> h; z = relu(A_hat h + b2) ---
    gemm_kernel<64, 64, 4, false><<<ceil_div(N, 64), 256, SM_L2>>>(abuf, W2, nullptr, hbuf, N);
    agg_gather_kernel<true, true><<<ceil_div(N, 16), 256>>>(hbuf, b2, z, N);

    // --- layer 3: z@W3 -> h; abuf = relu(A_hat h + b3) ---
    gemm_kernel<64, 64, 4, false><<<ceil_div(N, 64), 256, SM_L2>>>(z, W3, nullptr, hbuf, N);
    agg_gather_kernel<true, true><<<ceil_div(N, 16), 256>>>(hbuf, b3, abuf, N);

    // --- layer 4: hbuf = A_hat abuf; x_hat = hbuf@W4 + b4 ---
    agg_gather_kernel<false, false><<<ceil_div(N, 16), 256>>>(abuf, nullptr, hbuf, N);
    gemm_kernel<64, 128, 4, true><<<ceil_div(N, 32), 256, SM_L4>>>(hbuf, W4, b4, xhat, N);
}